// round 16
// baseline (speedup 1.0000x reference)
#include <cuda_runtime.h>
#include <cuda_bf16.h>
#include <cstdint>

// DeformConv3d 'HW' (t-offset == 0 -> 2D bilinear at integer t).
// R16 = R15 (HMMA bf16 hi/lo split, 1 warp/block, B frags from L1-resident
// global, pair-pipelined staging) with m16 tiles: warp = 16 points, 2 lanes
// per point (lane parity takes c-groups {0,1} / {2,3}). Grid 4096 -> ~28
// warps/SM (was 13.8); per-lane regs halve so residency is no longer RF-bound.

#define NB  2
#define NC  16
#define NT  8
#define NH  64
#define NW  64
#define NCO 16
#define NK  27
#define HW  (NH * NW)
#define THW (NT * HW)

#define FMA2(d, a, b) \
    asm("fma.rn.f32x2 %0, %1, %2, %0;" : "+l"(d) : "l"(a), "l"(b))
#define PACKB(d, s) \
    asm("mov.b64 %0, {%1, %1};" : "=l"(d) : "f"(s))
#define UNPACK2(lo, hi, s) \
    asm("mov.b64 {%0, %1}, %2;" : "=f"(lo), "=f"(hi) : "l"(s))

#define MMA16816(D, A, B) \
    asm volatile("mma.sync.aligned.m16n8k16.row.col.f32.bf16.bf16.f32 " \
        "{%0,%1,%2,%3}, {%4,%5,%6,%7}, {%8,%9}, {%0,%1,%2,%3};" \
        : "+f"((D)[0]), "+f"((D)[1]), "+f"((D)[2]), "+f"((D)[3]) \
        : "r"((A)[0]), "r"((A)[1]), "r"((A)[2]), "r"((A)[3]), \
          "r"((B).x), "r"((B).y))

#define LDM4(R, ADDR) \
    asm volatile("ldmatrix.sync.aligned.m8n8.x4.shared.b16 {%0,%1,%2,%3}, [%4];" \
        : "=r"((R)[0]), "=r"((R)[1]), "=r"((R)[2]), "=r"((R)[3]) : "r"(ADDR))

static __device__ __forceinline__ uint32_t smem_u32(const void* p) {
    uint32_t a;
    asm("{ .reg .u64 t; cvta.to.shared.u64 t, %1; cvt.u32.u64 %0, t; }"
        : "=r"(a) : "l"(p));
    return a;
}

// ---------------------------------------------------------------------------
// scratch
__device__ __align__(16) float g_x4[NB * NT * 4 * HW * 4]; // c4 channels-last x
__device__ __align__(16) uint2 g_bfrag[NK * 2 * 2 * 32];   // B mma fragments

// fused pre-pass: blocks < 1024 transpose x; blocks >= 1024 pack B fragments.
__global__ void prep_kernel(const float* __restrict__ x,
                            const float* __restrict__ wgt)
{
    if (blockIdx.x < 1024) {
        const int tid = blockIdx.x * 256 + threadIdx.x;   // 0..262143
        const int hw = tid & (HW - 1);
        const int g  = (tid >> 12) & 3;
        const int t  = (tid >> 14) & 7;
        const int b  = tid >> 17;
        float4 v;
        v.x = __ldg(&x[((b * NC + 4 * g + 0) * NT + t) * HW + hw]);
        v.y = __ldg(&x[((b * NC + 4 * g + 1) * NT + t) * HW + hw]);
        v.z = __ldg(&x[((b * NC + 4 * g + 2) * NT + t) * HW + hw]);
        v.w = __ldg(&x[((b * NC + 4 * g + 3) * NT + t) * HW + hw]);
        reinterpret_cast<float4*>(g_x4)[tid] = v;
    } else {
        // B fragment pack (verified R9): g_bfrag[tap][split][ntile][lane];
        // lane l: b.x = {B[2(l%4)][n], B[2(l%4)+1][n]}, b.y = {B[+8][n],
        // B[+9][n]}, n = nt*8 + l/4, B[c][co] = w[co][c][tap].
        const int i = (blockIdx.x - 1024) * 256 + threadIdx.x;
        if (i >= NK * 2 * 2 * 32) return;
        const int l  = i & 31;
        const int nt = (i >> 5) & 1;
        const int s  = (i >> 6) & 1;
        const int k  = i >> 7;
        const int n  = nt * 8 + (l >> 2);
        const int kp = (l & 3) * 2;
        __nv_bfloat16 e[4];
#pragma unroll
        for (int j = 0; j < 4; j++) {
            const int c = kp + (j & 1) + (j >> 1) * 8;
            const float v = wgt[(n * NC + c) * NK + k];
            const __nv_bfloat16 hi = __float2bfloat16(v);
            e[j] = s ? __float2bfloat16(v - __bfloat162float(hi)) : hi;
        }
        __nv_bfloat162 r0 = __halves2bfloat162(e[0], e[1]);
        __nv_bfloat162 r1 = __halves2bfloat162(e[2], e[3]);
        uint2 o;
        o.x = *reinterpret_cast<uint32_t*>(&r0);
        o.y = *reinterpret_cast<uint32_t*>(&r1);
        g_bfrag[i] = o;
    }
}

// ---------------------------------------------------------------------------
// per-tap gather + bilinear + bf16 hi/lo split for THIS LANE's 2 c-groups
// (groups 2*par, 2*par+1). Both lanes of a point pair read the same offsets
// (broadcast). Produces hi[4], lo[4] = 16B each.
static __device__ __forceinline__ void gather_tap(
    const ulonglong2* __restrict__ pl, const float* __restrict__ tb,
    int k, int kh, int kw, int h, int w, int par,
    uint32_t hi[4], uint32_t lo[4])
{
    const float offh = __ldg(tb + (2 * k) * THW);
    const float offw = __ldg(tb + (2 * k + 1) * THW);

    const float ph = (float)(h - 1 + kh) + offh;
    const float pw = (float)(w - 1 + kw) + offw;
    const int h0 = __float2int_rd(ph);
    const int w0 = __float2int_rd(pw);
    const float fh = ph - (float)h0;
    const float fw = pw - (float)w0;
    const int h1 = h0 + 1, w1 = w0 + 1;
    const bool vh0 = (h0 >= 0) & (h0 < NH);
    const bool vh1 = (h1 >= 0) & (h1 < NH);
    const bool vw0 = (w0 >= 0) & (w0 < NW);
    const bool vw1 = (w1 >= 0) & (w1 < NW);
    const float gh0 = 1.0f - fh, gw0 = 1.0f - fw;
    const float c00 = (vh0 & vw0) ? gh0 * gw0 : 0.0f;
    const float c01 = (vh0 & vw1) ? gh0 * fw  : 0.0f;
    const float c10 = (vh1 & vw0) ? fh  * gw0 : 0.0f;
    const float c11 = (vh1 & vw1) ? fh  * fw  : 0.0f;
    const int h0c = min(max(h0, 0), NH - 1);
    const int h1c = min(max(h1, 0), NH - 1);
    const int w0c = min(max(w0, 0), NW - 1);
    const int w1c = min(max(w1, 0), NW - 1);
    const int i00 = h0c * NW + w0c;
    const int i01 = h0c * NW + w1c;
    const int i10 = h1c * NW + w0c;
    const int i11 = h1c * NW + w1c;

    unsigned long long cc00, cc01, cc10, cc11;
    PACKB(cc00, c00); PACKB(cc01, c01);
    PACKB(cc10, c10); PACKB(cc11, c11);

#pragma unroll
    for (int gg = 0; gg < 2; gg++) {
        const ulonglong2* __restrict__ pg = pl + (2 * par + gg) * HW;
        unsigned long long u0 = 0ULL, u1 = 0ULL;
        { const ulonglong2 a = __ldg(pg + i00);
          FMA2(u0, cc00, a.x); FMA2(u1, cc00, a.y); }
        { const ulonglong2 a = __ldg(pg + i01);
          FMA2(u0, cc01, a.x); FMA2(u1, cc01, a.y); }
        { const ulonglong2 a = __ldg(pg + i10);
          FMA2(u0, cc10, a.x); FMA2(u1, cc10, a.y); }
        { const ulonglong2 a = __ldg(pg + i11);
          FMA2(u0, cc11, a.x); FMA2(u1, cc11, a.y); }
        float v0, v1, v2, v3;
        UNPACK2(v0, v1, u0);
        UNPACK2(v2, v3, u1);
        __nv_bfloat162 hA = __floats2bfloat162_rn(v0, v1); // .x = even c
        __nv_bfloat162 hB = __floats2bfloat162_rn(v2, v3);
        float2 fA = __bfloat1622float2(hA);
        float2 fB = __bfloat1622float2(hB);
        __nv_bfloat162 lA = __floats2bfloat162_rn(v0 - fA.x, v1 - fA.y);
        __nv_bfloat162 lB = __floats2bfloat162_rn(v2 - fB.x, v3 - fB.y);
        hi[2 * gg]     = *reinterpret_cast<uint32_t*>(&hA);
        hi[2 * gg + 1] = *reinterpret_cast<uint32_t*>(&hB);
        lo[2 * gg]     = *reinterpret_cast<uint32_t*>(&lA);
        lo[2 * gg + 1] = *reinterpret_cast<uint32_t*>(&lB);
    }
}

// staging row = point (16 rows x 80B): hi bytes [0,32), lo [32,64);
// lane parity selects the 16B half within each.
static __device__ __forceinline__ void sts_tap(
    uint32_t abuf, int p, int par, const uint32_t hi[4], const uint32_t lo[4])
{
    const uint32_t r = abuf + (uint32_t)p * 80 + (uint32_t)par * 16;
    asm volatile("st.shared.v4.b32 [%0], {%1,%2,%3,%4};"
        :: "r"(r), "r"(hi[0]), "r"(hi[1]), "r"(hi[2]), "r"(hi[3]) : "memory");
    asm volatile("st.shared.v4.b32 [%0], {%1,%2,%3,%4};"
        :: "r"(r + 32), "r"(lo[0]), "r"(lo[1]), "r"(lo[2]), "r"(lo[3]) : "memory");
}

// B fragments loaded directly from global (L1-resident 27.6KB table)
static __device__ __forceinline__ void mma_tap(
    uint32_t abuf, int k, int lane, float d[2][4])
{
    uint32_t ah[4], al[4];
    const uint32_t r0a = abuf + (uint32_t)(lane & 15) * 80
                       + (uint32_t)(lane >> 4) * 16;
    LDM4(ah, r0a);
    LDM4(al, r0a + 32);

    const uint2* __restrict__ bp = g_bfrag + k * 128 + lane;
    const uint2 bh0 = __ldg(bp);
    const uint2 bh1 = __ldg(bp + 32);
    const uint2 bl0 = __ldg(bp + 64);
    const uint2 bl1 = __ldg(bp + 96);

    MMA16816(d[0], ah, bh0); MMA16816(d[1], ah, bh1);
    MMA16816(d[0], al, bh0); MMA16816(d[1], al, bh1);
    MMA16816(d[0], ah, bl0); MMA16816(d[1], ah, bl1);
}

// ---------------------------------------------------------------------------
// main kernel: ONE WARP PER BLOCK, warp = 16 consecutive points (m16 tile),
// 2 lanes per point. Grid 4096 -> ~28 warps/SM.
// dynamic smem: two 1280B staging buffers.
#define STG_BYTES   1280
#define SMEM_BYTES  (2 * STG_BYTES)   // 2560

__global__ void __launch_bounds__(32, 24)
deform_conv3d_mma_kernel(const float* __restrict__ temp,
                         const float* __restrict__ bias,
                         float* __restrict__ out)
{
    extern __shared__ __align__(16) uint8_t dynsm[];

    const int lane = threadIdx.x;
    const int p    = lane >> 1;            // point within warp (0..15)
    const int par  = lane & 1;             // c-group half
    const int wpt  = blockIdx.x * 16;      // warp base point
    const int pt   = wpt + p;
    const int w = pt & 63;
    const int h = (pt >> 6) & 63;
    const int t = (pt >> 12) & 7;   // warp-uniform
    const int b = pt >> 15;         // warp-uniform
    const int sp = pt & (THW - 1);

    const uint32_t abuf0 = smem_u32(dynsm);
    const uint32_t abuf1 = abuf0 + STG_BYTES;
    const float* __restrict__ tb = temp + b * (2 * NK * THW) + sp;
    const ulonglong2* __restrict__ x4all =
        reinterpret_cast<const ulonglong2*>(g_x4) + b * NT * 4 * HW;

    float d[2][4];
#pragma unroll
    for (int n = 0; n < 2; n++)
#pragma unroll
        for (int j = 0; j < 4; j++) d[n][j] = 0.0f;

    for (int kt = 0; kt < 3; kt++) {
        const int ti = t - 1 + kt;
        if (ti < 0 || ti >= NT) continue;            // warp-uniform branch
        const ulonglong2* __restrict__ pl = x4all + ti * 4 * HW;
        const int kb = kt * 9;

        // 4 pipelined pairs + 1 tail tap (R12 structure)
#pragma unroll
        for (int pp = 0; pp < 4; pp++) {
            const int kk0 = 2 * pp;
            const int kk1 = kk0 + 1;
            uint32_t hiA[4], loA[4], hiB[4], loB[4];
            gather_tap(pl, tb, kb + kk0, kk0 / 3, kk0 % 3, h, w, par, hiA, loA);
            gather_tap(pl, tb, kb + kk1, kk1 / 3, kk1 % 3, h, w, par, hiB, loB);
            sts_tap(abuf0, p, par, hiA, loA);
            sts_tap(abuf1, p, par, hiB, loB);
            __syncwarp();                      // RAW for ldmatrix
            mma_tap(abuf0, kb + kk0, lane, d);
            mma_tap(abuf1, kb + kk1, lane, d);
            __syncwarp();                      // WAR before next pair's STS
        }
        {
            uint32_t hiA[4], loA[4];
            gather_tap(pl, tb, kb + 8, 2, 2, h, w, par, hiA, loA);
            sts_tap(abuf0, p, par, hiA, loA);
            __syncwarp();
            mma_tap(abuf0, kb + 8, lane, d);
            __syncwarp();
        }
    }

    // epilogue: D (m16n8) per ntile: lane -> rows {l/4, l/4+8}, cols {2(l%4),+1}
    const int r0 = lane >> 2;
    const int cp = (lane & 3) * 2;
    const float bv[4] = { __ldg(bias + cp),     __ldg(bias + cp + 1),
                          __ldg(bias + cp + 8), __ldg(bias + cp + 9) };
    const int wsp = wpt & (THW - 1);
    float* __restrict__ ob = out + b * (NCO * THW) + wsp;
#pragma unroll
    for (int n = 0; n < 2; n++) {
        const int col = n * 8 + cp;
        ob[(col)     * THW + r0]     = d[n][0] + bv[n * 2 + 0];
        ob[(col + 1) * THW + r0]     = d[n][1] + bv[n * 2 + 1];
        ob[(col)     * THW + r0 + 8] = d[n][2] + bv[n * 2 + 0];
        ob[(col + 1) * THW + r0 + 8] = d[n][3] + bv[n * 2 + 1];
    }
}

extern "C" void kernel_launch(void* const* d_in, const int* in_sizes, int n_in,
                              void* d_out, int out_size)
{
    const float* x    = (const float*)d_in[0];
    const float* temp = (const float*)d_in[1];
    const float* wgt  = (const float*)d_in[2];
    const float* bias = (const float*)d_in[3];
    float* out = (float*)d_out;

    prep_kernel<<<1024 + 14, 256>>>(x, wgt);
    deform_conv3d_mma_kernel<<<(NB * THW) / 16, 32, SMEM_BYTES>>>(
        temp, bias, out);
}

// round 17
// speedup vs baseline: 1.8477x; 1.8477x over previous
#include <cuda_runtime.h>
#include <cuda_bf16.h>
#include <cstdint>

// DeformConv3d 'HW' (t-offset == 0 -> 2D bilinear at integer t).
// R17 = R15 (HMMA bf16 hi/lo split, 1 warp/block = 32 points, B frags from
// L1-resident global, pair-pipelined staging) with COOPERATIVE GATHER ROUNDS:
// per round, lane l handles (point 8r + l>>2, c-group l&3), redundantly
// recomputing that point's bilinear setup. With x in interleaved [hw][g]
// layout, each corner LDG's lanes cover ~512B contiguous -> ~4-8 cache lines
// per LDG instead of ~16. Trades idle ALU for the saturated L1 pipe.

#define NB  2
#define NC  16
#define NT  8
#define NH  64
#define NW  64
#define NCO 16
#define NK  27
#define HW  (NH * NW)
#define THW (NT * HW)

#define FMA2(d, a, b) \
    asm("fma.rn.f32x2 %0, %1, %2, %0;" : "+l"(d) : "l"(a), "l"(b))
#define PACKB(d, s) \
    asm("mov.b64 %0, {%1, %1};" : "=l"(d) : "f"(s))
#define UNPACK2(lo, hi, s) \
    asm("mov.b64 {%0, %1}, %2;" : "=f"(lo), "=f"(hi) : "l"(s))

#define MMA16816(D, A, B) \
    asm volatile("mma.sync.aligned.m16n8k16.row.col.f32.bf16.bf16.f32 " \
        "{%0,%1,%2,%3}, {%4,%5,%6,%7}, {%8,%9}, {%0,%1,%2,%3};" \
        : "+f"((D)[0]), "+f"((D)[1]), "+f"((D)[2]), "+f"((D)[3]) \
        : "r"((A)[0]), "r"((A)[1]), "r"((A)[2]), "r"((A)[3]), \
          "r"((B).x), "r"((B).y))

#define LDM4(R, ADDR) \
    asm volatile("ldmatrix.sync.aligned.m8n8.x4.shared.b16 {%0,%1,%2,%3}, [%4];" \
        : "=r"((R)[0]), "=r"((R)[1]), "=r"((R)[2]), "=r"((R)[3]) : "r"(ADDR))

static __device__ __forceinline__ uint32_t smem_u32(const void* p) {
    uint32_t a;
    asm("{ .reg .u64 t; cvta.to.shared.u64 t, %1; cvt.u32.u64 %0, t; }"
        : "=r"(a) : "l"(p));
    return a;
}

// ---------------------------------------------------------------------------
// scratch: x4 interleaved channels-last [b][t][hw][g] (g = c/4, float4 each)
__device__ __align__(16) float g_x4[NB * NT * HW * 4 * 4];
__device__ __align__(16) uint2 g_bfrag[NK * 2 * 2 * 32];   // B mma fragments

// fused pre-pass: blocks < 1024 transpose x; blocks >= 1024 pack B fragments.
__global__ void prep_kernel(const float* __restrict__ x,
                            const float* __restrict__ wgt)
{
    if (blockIdx.x < 1024) {
        const int tid = blockIdx.x * 256 + threadIdx.x;   // 0..262143
        const int hw = tid & (HW - 1);
        const int g  = (tid >> 12) & 3;
        const int t  = (tid >> 14) & 7;
        const int b  = tid >> 17;
        float4 v;
        v.x = __ldg(&x[((b * NC + 4 * g + 0) * NT + t) * HW + hw]);
        v.y = __ldg(&x[((b * NC + 4 * g + 1) * NT + t) * HW + hw]);
        v.z = __ldg(&x[((b * NC + 4 * g + 2) * NT + t) * HW + hw]);
        v.w = __ldg(&x[((b * NC + 4 * g + 3) * NT + t) * HW + hw]);
        // interleaved: granule index = ((b*NT + t)*HW + hw)*4 + g
        const int oi = ((((b * NT + t) * HW) + hw) << 2) + g;
        reinterpret_cast<float4*>(g_x4)[oi] = v;
    } else {
        // B fragment pack (verified R9): g_bfrag[tap][split][ntile][lane];
        // lane l: b.x = {B[2(l%4)][n], B[2(l%4)+1][n]}, b.y = {B[+8][n],
        // B[+9][n]}, n = nt*8 + l/4, B[c][co] = w[co][c][tap].
        const int i = (blockIdx.x - 1024) * 256 + threadIdx.x;
        if (i >= NK * 2 * 2 * 32) return;
        const int l  = i & 31;
        const int nt = (i >> 5) & 1;
        const int s  = (i >> 6) & 1;
        const int k  = i >> 7;
        const int n  = nt * 8 + (l >> 2);
        const int kp = (l & 3) * 2;
        __nv_bfloat16 e[4];
#pragma unroll
        for (int j = 0; j < 4; j++) {
            const int c = kp + (j & 1) + (j >> 1) * 8;
            const float v = wgt[(n * NC + c) * NK + k];
            const __nv_bfloat16 hi = __float2bfloat16(v);
            e[j] = s ? __float2bfloat16(v - __bfloat162float(hi)) : hi;
        }
        __nv_bfloat162 r0 = __halves2bfloat162(e[0], e[1]);
        __nv_bfloat162 r1 = __halves2bfloat162(e[2], e[3]);
        uint2 o;
        o.x = *reinterpret_cast<uint32_t*>(&r0);
        o.y = *reinterpret_cast<uint32_t*>(&r1);
        g_bfrag[i] = o;
    }
}

// ---------------------------------------------------------------------------
// cooperative gather + bilinear + bf16 split + store, one tap.
// lane l -> (p_sub = l>>2, g = l&3); 4 rounds cover points 8r+p_sub.
// Each lane recomputes its round-point's bilinear setup (redundant ALU),
// loads granule g of each corner (dense addresses), combines, splits, stores
// 8B hi + 8B lo into staging row p.
static __device__ __forceinline__ void gather_store_tap(
    const ulonglong2* __restrict__ pl,   // plane granule base ([hw][g])
    const float* __restrict__ tbb,       // temp + b*2K*THW + spbase
    int k, int kh, int kw, int h, int wbase, int p_sub, int g,
    uint32_t abuf)
{
#pragma unroll
    for (int r = 0; r < 4; r++) {
        const int p = 8 * r + p_sub;
        const int w = wbase + p;

        const float offh = __ldg(tbb + (2 * k) * THW + p);
        const float offw = __ldg(tbb + (2 * k + 1) * THW + p);

        const float ph = (float)(h - 1 + kh) + offh;
        const float pw = (float)(w - 1 + kw) + offw;
        const int h0 = __float2int_rd(ph);
        const int w0 = __float2int_rd(pw);
        const float fh = ph - (float)h0;
        const float fw = pw - (float)w0;
        const int h1 = h0 + 1, w1 = w0 + 1;
        const bool vh0 = (h0 >= 0) & (h0 < NH);
        const bool vh1 = (h1 >= 0) & (h1 < NH);
        const bool vw0 = (w0 >= 0) & (w0 < NW);
        const bool vw1 = (w1 >= 0) & (w1 < NW);
        const float gh0 = 1.0f - fh, gw0 = 1.0f - fw;
        const float c00 = (vh0 & vw0) ? gh0 * gw0 : 0.0f;
        const float c01 = (vh0 & vw1) ? gh0 * fw  : 0.0f;
        const float c10 = (vh1 & vw0) ? fh  * gw0 : 0.0f;
        const float c11 = (vh1 & vw1) ? fh  * fw  : 0.0f;
        const int h0c = min(max(h0, 0), NH - 1);
        const int h1c = min(max(h1, 0), NH - 1);
        const int w0c = min(max(w0, 0), NW - 1);
        const int w1c = min(max(w1, 0), NW - 1);
        const int i00 = h0c * NW + w0c;
        const int i01 = h0c * NW + w1c;
        const int i10 = h1c * NW + w0c;
        const int i11 = h1c * NW + w1c;

        unsigned long long cc00, cc01, cc10, cc11;
        PACKB(cc00, c00); PACKB(cc01, c01);
        PACKB(cc10, c10); PACKB(cc11, c11);

        unsigned long long u0 = 0ULL, u1 = 0ULL;
        { const ulonglong2 a = __ldg(pl + i00 * 4 + g);
          FMA2(u0, cc00, a.x); FMA2(u1, cc00, a.y); }
        { const ulonglong2 a = __ldg(pl + i01 * 4 + g);
          FMA2(u0, cc01, a.x); FMA2(u1, cc01, a.y); }
        { const ulonglong2 a = __ldg(pl + i10 * 4 + g);
          FMA2(u0, cc10, a.x); FMA2(u1, cc10, a.y); }
        { const ulonglong2 a = __ldg(pl + i11 * 4 + g);
          FMA2(u0, cc11, a.x); FMA2(u1, cc11, a.y); }

        float v0, v1, v2, v3;
        UNPACK2(v0, v1, u0);
        UNPACK2(v2, v3, u1);
        __nv_bfloat162 hA = __floats2bfloat162_rn(v0, v1); // .x = even c
        __nv_bfloat162 hB = __floats2bfloat162_rn(v2, v3);
        float2 fA = __bfloat1622float2(hA);
        float2 fB = __bfloat1622float2(hB);
        __nv_bfloat162 lA = __floats2bfloat162_rn(v0 - fA.x, v1 - fA.y);
        __nv_bfloat162 lB = __floats2bfloat162_rn(v2 - fB.x, v3 - fB.y);
        const uint32_t hi0 = *reinterpret_cast<uint32_t*>(&hA);
        const uint32_t hi1 = *reinterpret_cast<uint32_t*>(&hB);
        const uint32_t lo0 = *reinterpret_cast<uint32_t*>(&lA);
        const uint32_t lo1 = *reinterpret_cast<uint32_t*>(&lB);

        // staging row p (80B): ch c hi at byte 2c, lo at 32 + 2c; group g
        // occupies bytes [8g, 8g+8).
        const uint32_t rr = abuf + (uint32_t)p * 80 + (uint32_t)g * 8;
        asm volatile("st.shared.v2.b32 [%0], {%1,%2};"
                     :: "r"(rr), "r"(hi0), "r"(hi1) : "memory");
        asm volatile("st.shared.v2.b32 [%0], {%1,%2};"
                     :: "r"(rr + 32), "r"(lo0), "r"(lo1) : "memory");
    }
}

// B fragments loaded directly from global (L1-resident 27.6KB table)
static __device__ __forceinline__ void mma_tap(
    uint32_t abuf, int k, int lane, float d[2][2][4])
{
    uint32_t ah[2][4], al[2][4];
    const uint32_t r0a = abuf + (uint32_t)(lane & 15) * 80
                       + (uint32_t)(lane >> 4) * 16;
    LDM4(ah[0], r0a);
    LDM4(ah[1], r0a + 16 * 80);
    LDM4(al[0], r0a + 32);
    LDM4(al[1], r0a + 16 * 80 + 32);

    const uint2* __restrict__ bp = g_bfrag + k * 128 + lane;
    const uint2 bh0 = __ldg(bp);
    const uint2 bh1 = __ldg(bp + 32);
    const uint2 bl0 = __ldg(bp + 64);
    const uint2 bl1 = __ldg(bp + 96);

    MMA16816(d[0][0], ah[0], bh0); MMA16816(d[0][1], ah[0], bh1);
    MMA16816(d[1][0], ah[1], bh0); MMA16816(d[1][1], ah[1], bh1);
    MMA16816(d[0][0], al[0], bh0); MMA16816(d[0][1], al[0], bh1);
    MMA16816(d[1][0], al[1], bh0); MMA16816(d[1][1], al[1], bh1);
    MMA16816(d[0][0], ah[0], bl0); MMA16816(d[0][1], ah[0], bl1);
    MMA16816(d[1][0], ah[1], bl0); MMA16816(d[1][1], ah[1], bl1);
}

// ---------------------------------------------------------------------------
// main kernel: ONE WARP PER BLOCK (32 threads), warp = 32 consecutive points
// (one half w-row: h is warp-uniform). dynamic smem: two 2560B staging bufs.
#define STG_BYTES   2560
#define SMEM_BYTES  (2 * STG_BYTES)   // 5120

__global__ void __launch_bounds__(32, 16)
deform_conv3d_mma_kernel(const float* __restrict__ temp,
                         const float* __restrict__ bias,
                         float* __restrict__ out)
{
    extern __shared__ __align__(16) uint8_t dynsm[];

    const int lane  = threadIdx.x;
    const int p_sub = lane >> 2;        // cooperative-gather point sub-index
    const int g     = lane & 3;         // cooperative-gather c-group
    const int wpt   = blockIdx.x * 32;  // warp base point
    const int pt    = wpt + lane;
    const int wbase = wpt & 63;             // 0 or 32 (h uniform per warp)
    const int h = (wpt >> 6) & 63;
    const int t = (wpt >> 12) & 7;   // warp-uniform
    const int b = wpt >> 15;         // warp-uniform
    const int spbase = wpt & (THW - 1);

    const uint32_t abuf0 = smem_u32(dynsm);
    const uint32_t abuf1 = abuf0 + STG_BYTES;
    const float* __restrict__ tbb = temp + b * (2 * NK * THW) + spbase;
    const ulonglong2* __restrict__ x4all =
        reinterpret_cast<const ulonglong2*>(g_x4) + b * NT * HW * 4;

    float d[2][2][4];
#pragma unroll
    for (int m = 0; m < 2; m++)
#pragma unroll
        for (int n = 0; n < 2; n++)
#pragma unroll
            for (int j = 0; j < 4; j++) d[m][n][j] = 0.0f;

    for (int kt = 0; kt < 3; kt++) {
        const int ti = t - 1 + kt;
        if (ti < 0 || ti >= NT) continue;            // warp-uniform branch
        const ulonglong2* __restrict__ pl = x4all + ti * HW * 4;
        const int kb = kt * 9;

        // 4 pipelined pairs + 1 tail tap (R12/R15 structure)
#pragma unroll
        for (int pp = 0; pp < 4; pp++) {
            const int kk0 = 2 * pp;
            const int kk1 = kk0 + 1;
            gather_store_tap(pl, tbb, kb + kk0, kk0 / 3, kk0 % 3,
                             h, wbase, p_sub, g, abuf0);
            gather_store_tap(pl, tbb, kb + kk1, kk1 / 3, kk1 % 3,
                             h, wbase, p_sub, g, abuf1);
            __syncwarp();                      // RAW for ldmatrix
            mma_tap(abuf0, kb + kk0, lane, d);
            mma_tap(abuf1, kb + kk1, lane, d);
            __syncwarp();                      // WAR before next pair's STS
        }
        {
            gather_store_tap(pl, tbb, kb + 8, 2, 2,
                             h, wbase, p_sub, g, abuf0);
            __syncwarp();
            mma_tap(abuf0, kb + 8, lane, d);
            __syncwarp();
        }
    }

    // epilogue: D frag (m16n8): lane -> rows {l/4, l/4+8}, cols {2(l%4), +1}
    const int r0 = lane >> 2;
    const int cp = (lane & 3) * 2;
    const float bv[4] = { __ldg(bias + cp),     __ldg(bias + cp + 1),
                          __ldg(bias + cp + 8), __ldg(bias + cp + 9) };
    float* __restrict__ ob = out + b * (NCO * THW) + spbase;
#pragma unroll
    for (int m = 0; m < 2; m++)
#pragma unroll
        for (int n = 0; n < 2; n++) {
            const int col = n * 8 + cp;
            const int row = 16 * m + r0;
            ob[(col)     * THW + row]     = d[m][n][0] + bv[n * 2 + 0];
            ob[(col + 1) * THW + row]     = d[m][n][1] + bv[n * 2 + 1];
            ob[(col)     * THW + row + 8] = d[m][n][2] + bv[n * 2 + 0];
            ob[(col + 1) * THW + row + 8] = d[m][n][3] + bv[n * 2 + 1];
        }
}

extern "C" void kernel_launch(void* const* d_in, const int* in_sizes, int n_in,
                              void* d_out, int out_size)
{
    const float* x    = (const float*)d_in[0];
    const float* temp = (const float*)d_in[1];
    const float* wgt  = (const float*)d_in[2];
    const float* bias = (const float*)d_in[3];
    float* out = (float*)d_out;

    prep_kernel<<<1024 + 14, 256>>>(x, wgt);
    deform_conv3d_mma_kernel<<<(NB * THW) / 32, 32, SMEM_BYTES>>>(
        temp, bias, out);
}